// round 4
// baseline (speedup 1.0000x reference)
#include <cuda_runtime.h>
#include <cuda_bf16.h>
#include <cstdint>
#include <math.h>

#define DIMD   2048
#define HIDDEN 4096
#define BATCH  4
#define SEQ    2048
#define MROWS  (BATCH * SEQ)   // 8192

// ---------------------------------------------------------------------------
// Scratch (static device arrays; no allocations anywhere)
// ---------------------------------------------------------------------------
__device__ __nv_bfloat16 g_Ae1[(size_t)MROWS  * 2 * DIMD];    // x split      [8192, 4096]
__device__ __nv_bfloat16 g_Be1[(size_t)HIDDEN * 2 * DIMD];    // W_in split   [4096, 4096]
__device__ float         g_u  [(size_t)MROWS * HIDDEN];       // u fp32       [8192, 4096]
__device__ __nv_bfloat16 g_As2[(size_t)MROWS  * 2 * HIDDEN];  // states split [8192, 8192]
__device__ __nv_bfloat16 g_Be2[(size_t)DIMD   * 2 * HIDDEN];  // W_out split  [2048, 8192]

__device__ __forceinline__ uint32_t smem_u32(const void* p) {
    uint32_t a;
    asm("{ .reg .u64 t; cvta.to.shared.u64 t, %1; cvt.u32.u64 %0, t; }" : "=r"(a) : "l"(p));
    return a;
}

#define SW128(o) ((o) ^ (((o) >> 3) & 0x70))

__device__ __forceinline__ void cp16(uint32_t s, const void* g) {
    asm volatile("cp.async.cg.shared.global [%0], [%1], 16;" :: "r"(s), "l"(g));
}

__device__ __forceinline__ void ldsm_x4(uint32_t* r, uint32_t addr) {
    asm volatile("ldmatrix.sync.aligned.m8n8.x4.shared.b16 {%0,%1,%2,%3}, [%4];"
                 : "=r"(r[0]), "=r"(r[1]), "=r"(r[2]), "=r"(r[3]) : "r"(addr));
}

__device__ __forceinline__ void mma16816(float* c, const uint32_t* a, const uint32_t* b) {
    asm volatile(
        "mma.sync.aligned.m16n8k16.row.col.f32.bf16.bf16.f32 "
        "{%0,%1,%2,%3}, {%4,%5,%6,%7}, {%8,%9}, {%0,%1,%2,%3};"
        : "+f"(c[0]), "+f"(c[1]), "+f"(c[2]), "+f"(c[3])
        : "r"(a[0]), "r"(a[1]), "r"(a[2]), "r"(a[3]), "r"(b[0]), "r"(b[1]));
}

// ---------------------------------------------------------------------------
// bf16 mma.sync GEMM (NT): C[M,N] = Asplit[M,2K] x Bsplit[N,2K]^T (3 products) + bias
// CTA tile 128x128, 8 warps (2x4), warp tile 64x32, K-stage = 64 bf16 (128B SW128
// rows), 3-stage cp.async pipeline, register double-buffered fragments.
// ---------------------------------------------------------------------------
#define STAGE_BYTES 32768   // A 16KB + B 16KB

__global__ __launch_bounds__(256, 2)
void gemm_mma(const __nv_bfloat16* __restrict__ A, const __nv_bfloat16* __restrict__ B,
              const float* __restrict__ bias, float* __restrict__ C,
              int N, int K, int KT)
{
    extern __shared__ char dyn[];
    uint32_t base = (smem_u32(dyn) + 1023) & ~1023u;

    const int tid  = threadIdx.x;
    const int lane = tid & 31;
    const int wid  = tid >> 5;
    const int wm   = wid >> 2;    // 0..1
    const int wn   = wid & 3;     // 0..3

    const int ntile = blockIdx.x, mtile = blockIdx.y;
    const int sps = K / 64;                    // stages per split segment
    const size_t pitch = (size_t)4 * K;        // bytes per row (2K bf16)
    const char* Abase = (const char*)A + (size_t)(mtile * 128) * pitch;
    const char* Bbase = (const char*)B + (size_t)(ntile * 128) * pitch;

    // cp.async loader mapping: 1024 16B-chunks per (A|B) tile, 256 threads -> 4 each
    auto load_stage = [&](int st) {
        int seg = st / sps;
        int kk  = (st - seg * sps) * 64;
        int ka  = kk + (seg == 1 ? K : 0);     // segment1: A_lo x B_hi
        int kb  = kk + (seg == 2 ? K : 0);     // segment2: A_hi x B_lo
        uint32_t sa = base + (uint32_t)(st % 3) * STAGE_BYTES;
        uint32_t sb = sa + 16384u;
        const char* ga = Abase + (size_t)ka * 2;
        const char* gb = Bbase + (size_t)kb * 2;
        #pragma unroll
        for (int i = 0; i < 4; i++) {
            int lin = tid + i * 256; int row = lin >> 3; int c = (lin & 7) * 16;
            cp16(sa + SW128((uint32_t)(row * 128 + c)), ga + (size_t)row * pitch + c);
            cp16(sb + SW128((uint32_t)(row * 128 + c)), gb + (size_t)row * pitch + c);
        }
    };

    // ldmatrix lane addressing (offsets within the 128-row x 128B tile)
    const int g = lane >> 3, r = lane & 7;
    uint32_t aOff[4], bOff[2];
    {
        int aRow = r + (g & 1) * 8;
        int aCol = (g >> 1) * 16;
        #pragma unroll
        for (int mi = 0; mi < 4; mi++)
            aOff[mi] = (uint32_t)((wm * 64 + mi * 16 + aRow) * 128 + aCol);
        int bRow = r + (g >> 1) * 8;
        int bCol = (g & 1) * 16;
        #pragma unroll
        for (int nb = 0; nb < 2; nb++)
            bOff[nb] = (uint32_t)((wn * 32 + nb * 16 + bRow) * 128 + bCol);
    }

    float acc[4][4][4];
    #pragma unroll
    for (int mi = 0; mi < 4; mi++)
        #pragma unroll
        for (int nf = 0; nf < 4; nf++)
            #pragma unroll
            for (int q = 0; q < 4; q++)
                acc[mi][nf][q] = 0.f;

    load_stage(0);
    asm volatile("cp.async.commit_group;" ::: "memory");
    load_stage(1);
    asm volatile("cp.async.commit_group;" ::: "memory");

    uint32_t a_regs[2][4][4], b_regs[2][2][4];

    for (int st = 0; st < KT; st++) {
        asm volatile("cp.async.wait_group %0;" :: "n"(1) : "memory");
        __syncthreads();

        if (st + 2 < KT) load_stage(st + 2);
        asm volatile("cp.async.commit_group;" ::: "memory");

        uint32_t sa = base + (uint32_t)(st % 3) * STAGE_BYTES;
        uint32_t sb = sa + 16384u;

        // Preload ks=0 fragments
        #pragma unroll
        for (int mi = 0; mi < 4; mi++) ldsm_x4(a_regs[0][mi], sa + SW128(aOff[mi]));
        #pragma unroll
        for (int nb = 0; nb < 2; nb++) ldsm_x4(b_regs[0][nb], sb + SW128(bOff[nb]));

        #pragma unroll
        for (int ks = 0; ks < 4; ks++) {
            const int cur = ks & 1, nxt = cur ^ 1;
            if (ks < 3) {
                #pragma unroll
                for (int mi = 0; mi < 4; mi++)
                    ldsm_x4(a_regs[nxt][mi], sa + SW128(aOff[mi] + (ks + 1) * 32));
                #pragma unroll
                for (int nb = 0; nb < 2; nb++)
                    ldsm_x4(b_regs[nxt][nb], sb + SW128(bOff[nb] + (ks + 1) * 32));
            }
            #pragma unroll
            for (int mi = 0; mi < 4; mi++)
                #pragma unroll
                for (int nf = 0; nf < 4; nf++)
                    mma16816(acc[mi][nf], a_regs[cur][mi], &b_regs[cur][nf >> 1][(nf & 1) * 2]);
        }
        __syncthreads();
    }

    // Epilogue: bias + store fp32
    const int rowq = lane >> 2, colq = (lane & 3) * 2;
    #pragma unroll
    for (int mi = 0; mi < 4; mi++) {
        int row0 = mtile * 128 + wm * 64 + mi * 16 + rowq;
        #pragma unroll
        for (int nf = 0; nf < 4; nf++) {
            int col = ntile * 128 + wn * 32 + nf * 8 + colq;
            float b0 = bias[col], b1 = bias[col + 1];
            float2 v0 = make_float2(acc[mi][nf][0] + b0, acc[mi][nf][1] + b1);
            float2 v1 = make_float2(acc[mi][nf][2] + b0, acc[mi][nf][3] + b1);
            *(float2*)(C + (size_t)row0 * N + col)       = v0;
            *(float2*)(C + (size_t)(row0 + 8) * N + col) = v1;
        }
    }
}

// ---------------------------------------------------------------------------
// fp32 -> (hi|lo) bf16 split, dst row pitch = 2K
// ---------------------------------------------------------------------------
__global__ void split_kernel(const float* __restrict__ src, __nv_bfloat16* __restrict__ dst,
                             int kshift, size_t total4)
{
    const int K = 1 << kshift;
    const size_t stride = (size_t)gridDim.x * blockDim.x;
    for (size_t i = (size_t)blockIdx.x * blockDim.x + threadIdx.x; i < total4; i += stride) {
        size_t e = i * 4;
        size_t rw = e >> kshift;
        int    k = (int)(e & (size_t)(K - 1));
        float4 v = *(const float4*)(src + e);
        __nv_bfloat16* d = dst + rw * (size_t)(2 * K) + k;
        float f[4] = {v.x, v.y, v.z, v.w};
        #pragma unroll
        for (int j = 0; j < 4; j++) {
            __nv_bfloat16 hi = __float2bfloat16(f[j]);
            d[j]     = hi;
            d[K + j] = __float2bfloat16(f[j] - __bfloat162float(hi));
        }
    }
}

// ---------------------------------------------------------------------------
// Recurrence: state = tanh(u_t + state*gamma + beta); writes split states.
// tanh.approx.f32 keeps the serial dependence chain at ~1 MUFU per step.
// ---------------------------------------------------------------------------
__device__ __forceinline__ float tanh_fast(float x) {
    float y;
    asm("tanh.approx.f32 %0, %1;" : "=f"(y) : "f"(x));
    return y;
}

__global__ __launch_bounds__(256)
void recurrence_split(const float* __restrict__ u, const float* __restrict__ gamma,
                      const float* __restrict__ beta, __nv_bfloat16* __restrict__ S)
{
    const int idx = blockIdx.x * blockDim.x + threadIdx.x;   // 0..B*H-1
    const int b = idx >> 12;
    const int h = idx & (HIDDEN - 1);
    const float g = gamma[h], be = beta[h];

    const float* up = u + (size_t)b * SEQ * HIDDEN + h;
    __nv_bfloat16* sp = S + (size_t)b * SEQ * (2 * HIDDEN) + h;

    float state = 0.f;
    const int U = 16;
    #pragma unroll 1
    for (int s0 = 0; s0 < SEQ; s0 += U) {
        float uv[U];
        #pragma unroll
        for (int i = 0; i < U; i++)
            uv[i] = up[(size_t)(s0 + i) * HIDDEN];
        #pragma unroll
        for (int i = 0; i < U; i++) {
            state = tanh_fast(uv[i] + fmaf(state, g, be));
            __nv_bfloat16 hi = __float2bfloat16(state);
            size_t off = (size_t)(s0 + i) * (2 * HIDDEN);
            sp[off]          = hi;
            sp[off + HIDDEN] = __float2bfloat16(state - __bfloat162float(hi));
        }
    }
}

// ---------------------------------------------------------------------------
// Launch
// ---------------------------------------------------------------------------
extern "C" void kernel_launch(void* const* d_in, const int* in_sizes, int n_in,
                              void* d_out, int out_size)
{
    const float* x     = (const float*)d_in[0];  // [B,S,D]
    const float* W_in  = (const float*)d_in[1];  // [H,D]
    const float* b_in  = (const float*)d_in[2];  // [H]
    const float* W_out = (const float*)d_in[3];  // [D,H]
    const float* b_out = (const float*)d_in[4];  // [D]
    const float* gamma = (const float*)d_in[5];  // [H]
    const float* beta  = (const float*)d_in[6];  // [H]
    float* y = (float*)d_out;                    // [B,S,D]

    __nv_bfloat16 *Ae1, *Be1, *As2, *Be2;
    float* u;
    cudaGetSymbolAddress((void**)&Ae1, g_Ae1);
    cudaGetSymbolAddress((void**)&Be1, g_Be1);
    cudaGetSymbolAddress((void**)&u,   g_u);
    cudaGetSymbolAddress((void**)&As2, g_As2);
    cudaGetSymbolAddress((void**)&Be2, g_Be2);

    const int smem_bytes = 3 * STAGE_BYTES + 1024;   // 99328
    cudaFuncSetAttribute(gemm_mma, cudaFuncAttributeMaxDynamicSharedMemorySize, smem_bytes);

    // Split conversions
    split_kernel<<<4096, 256>>>(x,     Ae1, 11, (size_t)MROWS  * DIMD   / 4);
    split_kernel<<<4096, 256>>>(W_in,  Be1, 11, (size_t)HIDDEN * DIMD   / 4);
    split_kernel<<<4096, 256>>>(W_out, Be2, 12, (size_t)DIMD   * HIDDEN / 4);

    // GEMM1: u = x @ W_in^T + b_in    (M=8192, N=4096, K=2048 -> KT=96)
    {
        dim3 grid(HIDDEN / 128, MROWS / 128);
        gemm_mma<<<grid, 256, smem_bytes>>>(Ae1, Be1, b_in, u, HIDDEN, DIMD, 3 * (DIMD / 64));
    }

    // Recurrence + split of states
    recurrence_split<<<(BATCH * HIDDEN) / 256, 256>>>(u, gamma, beta, As2);

    // GEMM2: y = states @ W_out^T + b_out  (M=8192, N=2048, K=4096 -> KT=192)
    {
        dim3 grid(DIMD / 128, MROWS / 128);
        gemm_mma<<<grid, 256, smem_bytes>>>(As2, Be2, b_out, y, DIMD, HIDDEN, 3 * (HIDDEN / 64));
    }
}

// round 5
// speedup vs baseline: 1.0213x; 1.0213x over previous
#include <cuda_runtime.h>
#include <cuda_bf16.h>
#include <cstdint>
#include <math.h>

#define DIMD   2048
#define HIDDEN 4096
#define BATCH  4
#define SEQ    2048
#define MROWS  (BATCH * SEQ)   // 8192

// ---------------------------------------------------------------------------
// Scratch (static device arrays; no allocations anywhere)
// ---------------------------------------------------------------------------
__device__ __nv_bfloat16 g_Ae1[(size_t)MROWS  * 2 * DIMD];    // x split      [8192, 4096]
__device__ __nv_bfloat16 g_Be1[(size_t)HIDDEN * 2 * DIMD];    // W_in split   [4096, 4096]
__device__ float         g_u  [(size_t)MROWS * HIDDEN];       // u fp32       [8192, 4096]
__device__ __nv_bfloat16 g_As2[(size_t)MROWS  * 2 * HIDDEN];  // states split [8192, 8192]
__device__ __nv_bfloat16 g_Be2[(size_t)DIMD   * 2 * HIDDEN];  // W_out split  [2048, 8192]

__device__ __forceinline__ uint32_t smem_u32(const void* p) {
    uint32_t a;
    asm("{ .reg .u64 t; cvta.to.shared.u64 t, %1; cvt.u32.u64 %0, t; }" : "=r"(a) : "l"(p));
    return a;
}

#define SW128(o) ((o) ^ (((o) >> 3) & 0x70))

__device__ __forceinline__ void cp16(uint32_t s, const void* g) {
    asm volatile("cp.async.cg.shared.global [%0], [%1], 16;" :: "r"(s), "l"(g));
}

__device__ __forceinline__ void ldsm_x4(uint32_t* r, uint32_t addr) {
    asm volatile("ldmatrix.sync.aligned.m8n8.x4.shared.b16 {%0,%1,%2,%3}, [%4];"
                 : "=r"(r[0]), "=r"(r[1]), "=r"(r[2]), "=r"(r[3]) : "r"(addr));
}

__device__ __forceinline__ void mma16816(float* c, const uint32_t* a, const uint32_t* b) {
    asm volatile(
        "mma.sync.aligned.m16n8k16.row.col.f32.bf16.bf16.f32 "
        "{%0,%1,%2,%3}, {%4,%5,%6,%7}, {%8,%9}, {%0,%1,%2,%3};"
        : "+f"(c[0]), "+f"(c[1]), "+f"(c[2]), "+f"(c[3])
        : "r"(a[0]), "r"(a[1]), "r"(a[2]), "r"(a[3]), "r"(b[0]), "r"(b[1]));
}

// ---------------------------------------------------------------------------
// bf16 mma.sync GEMM (NT): C[M,N] = Asplit[M,2K] x Bsplit[N,2K]^T (3 products) + bias
// CTA tile 128x128, 8 warps (2x4), warp tile 64x32, K-stage = 64 bf16 (128B SW128
// rows), 3-stage cp.async pipeline. B fragments hoisted for the whole stage
// (32 regs); A fragments single-buffered per ks.
// ---------------------------------------------------------------------------
#define STAGE_BYTES 32768   // A 16KB + B 16KB

__global__ __launch_bounds__(256, 2)
void gemm_mma(const __nv_bfloat16* __restrict__ A, const __nv_bfloat16* __restrict__ B,
              const float* __restrict__ bias, float* __restrict__ C,
              int N, int K, int KT)
{
    extern __shared__ char dyn[];
    uint32_t base = (smem_u32(dyn) + 1023) & ~1023u;

    const int tid  = threadIdx.x;
    const int lane = tid & 31;
    const int wid  = tid >> 5;
    const int wm   = wid >> 2;    // 0..1
    const int wn   = wid & 3;     // 0..3

    const int ntile = blockIdx.x, mtile = blockIdx.y;
    const int sps = K / 64;                    // stages per split segment
    const size_t pitch = (size_t)4 * K;        // bytes per row (2K bf16)
    const char* Abase = (const char*)A + (size_t)(mtile * 128) * pitch;
    const char* Bbase = (const char*)B + (size_t)(ntile * 128) * pitch;

    // cp.async loader mapping: 1024 16B-chunks per (A|B) tile, 256 threads -> 4 each
    auto load_stage = [&](int st) {
        int seg = st / sps;
        int kk  = (st - seg * sps) * 64;
        int ka  = kk + (seg == 1 ? K : 0);     // segment1: A_lo x B_hi
        int kb  = kk + (seg == 2 ? K : 0);     // segment2: A_hi x B_lo
        uint32_t sa = base + (uint32_t)(st % 3) * STAGE_BYTES;
        uint32_t sb = sa + 16384u;
        const char* ga = Abase + (size_t)ka * 2;
        const char* gb = Bbase + (size_t)kb * 2;
        #pragma unroll
        for (int i = 0; i < 4; i++) {
            int lin = tid + i * 256; int row = lin >> 3; int c = (lin & 7) * 16;
            cp16(sa + SW128((uint32_t)(row * 128 + c)), ga + (size_t)row * pitch + c);
            cp16(sb + SW128((uint32_t)(row * 128 + c)), gb + (size_t)row * pitch + c);
        }
    };

    // ldmatrix lane addressing (offsets within the 128-row x 128B tile)
    const int g = lane >> 3, r = lane & 7;
    uint32_t aOff[4], bOff[2];
    {
        int aRow = r + (g & 1) * 8;
        int aCol = (g >> 1) * 16;
        #pragma unroll
        for (int mi = 0; mi < 4; mi++)
            aOff[mi] = (uint32_t)((wm * 64 + mi * 16 + aRow) * 128 + aCol);
        int bRow = r + (g >> 1) * 8;
        int bCol = (g & 1) * 16;
        #pragma unroll
        for (int nb = 0; nb < 2; nb++)
            bOff[nb] = (uint32_t)((wn * 32 + nb * 16 + bRow) * 128 + bCol);
    }

    float acc[4][4][4];
    #pragma unroll
    for (int mi = 0; mi < 4; mi++)
        #pragma unroll
        for (int nf = 0; nf < 4; nf++)
            #pragma unroll
            for (int q = 0; q < 4; q++)
                acc[mi][nf][q] = 0.f;

    load_stage(0);
    asm volatile("cp.async.commit_group;" ::: "memory");
    load_stage(1);
    asm volatile("cp.async.commit_group;" ::: "memory");

    for (int st = 0; st < KT; st++) {
        asm volatile("cp.async.wait_group %0;" :: "n"(1) : "memory");
        __syncthreads();

        if (st + 2 < KT) load_stage(st + 2);
        asm volatile("cp.async.commit_group;" ::: "memory");

        uint32_t sa = base + (uint32_t)(st % 3) * STAGE_BYTES;
        uint32_t sb = sa + 16384u;

        // Hoist ALL B fragments for this stage (4 ks x 2 ldsm.x4 = 32 regs)
        uint32_t b_regs[4][2][4];
        #pragma unroll
        for (int ks = 0; ks < 4; ks++)
            #pragma unroll
            for (int nb = 0; nb < 2; nb++)
                ldsm_x4(b_regs[ks][nb], sb + SW128(bOff[nb] + ks * 32));

        #pragma unroll
        for (int ks = 0; ks < 4; ks++) {
            uint32_t a_regs[4][4];
            #pragma unroll
            for (int mi = 0; mi < 4; mi++)
                ldsm_x4(a_regs[mi], sa + SW128(aOff[mi] + ks * 32));
            #pragma unroll
            for (int mi = 0; mi < 4; mi++)
                #pragma unroll
                for (int nf = 0; nf < 4; nf++)
                    mma16816(acc[mi][nf], a_regs[mi], &b_regs[ks][nf >> 1][(nf & 1) * 2]);
        }
        __syncthreads();
    }

    // Epilogue: bias + store fp32
    const int rowq = lane >> 2, colq = (lane & 3) * 2;
    #pragma unroll
    for (int mi = 0; mi < 4; mi++) {
        int row0 = mtile * 128 + wm * 64 + mi * 16 + rowq;
        #pragma unroll
        for (int nf = 0; nf < 4; nf++) {
            int col = ntile * 128 + wn * 32 + nf * 8 + colq;
            float b0 = bias[col], b1 = bias[col + 1];
            float2 v0 = make_float2(acc[mi][nf][0] + b0, acc[mi][nf][1] + b1);
            float2 v1 = make_float2(acc[mi][nf][2] + b0, acc[mi][nf][3] + b1);
            *(float2*)(C + (size_t)row0 * N + col)       = v0;
            *(float2*)(C + (size_t)(row0 + 8) * N + col) = v1;
        }
    }
}

// ---------------------------------------------------------------------------
// fp32 -> (hi|lo) bf16 split, dst row pitch = 2K
// ---------------------------------------------------------------------------
__global__ void split_kernel(const float* __restrict__ src, __nv_bfloat16* __restrict__ dst,
                             int kshift, size_t total4)
{
    const int K = 1 << kshift;
    const size_t stride = (size_t)gridDim.x * blockDim.x;
    for (size_t i = (size_t)blockIdx.x * blockDim.x + threadIdx.x; i < total4; i += stride) {
        size_t e = i * 4;
        size_t rw = e >> kshift;
        int    k = (int)(e & (size_t)(K - 1));
        float4 v = *(const float4*)(src + e);
        __nv_bfloat16* d = dst + rw * (size_t)(2 * K) + k;
        float f[4] = {v.x, v.y, v.z, v.w};
        #pragma unroll
        for (int j = 0; j < 4; j++) {
            __nv_bfloat16 hi = __float2bfloat16(f[j]);
            d[j]     = hi;
            d[K + j] = __float2bfloat16(f[j] - __bfloat162float(hi));
        }
    }
}

// ---------------------------------------------------------------------------
// Recurrence: state = tanh(u_t + state*gamma + beta); writes split states.
// tanh.approx.f32 keeps the serial dependence chain at ~1 MUFU per step.
// 64-thread blocks -> 256 blocks so all 148 SMs participate.
// ---------------------------------------------------------------------------
__device__ __forceinline__ float tanh_fast(float x) {
    float y;
    asm("tanh.approx.f32 %0, %1;" : "=f"(y) : "f"(x));
    return y;
}

__global__ __launch_bounds__(64)
void recurrence_split(const float* __restrict__ u, const float* __restrict__ gamma,
                      const float* __restrict__ beta, __nv_bfloat16* __restrict__ S)
{
    const int idx = blockIdx.x * blockDim.x + threadIdx.x;   // 0..B*H-1
    const int b = idx >> 12;
    const int h = idx & (HIDDEN - 1);
    const float g = gamma[h], be = beta[h];

    const float* up = u + (size_t)b * SEQ * HIDDEN + h;
    __nv_bfloat16* sp = S + (size_t)b * SEQ * (2 * HIDDEN) + h;

    float state = 0.f;
    const int U = 16;
    #pragma unroll 1
    for (int s0 = 0; s0 < SEQ; s0 += U) {
        float uv[U];
        #pragma unroll
        for (int i = 0; i < U; i++)
            uv[i] = up[(size_t)(s0 + i) * HIDDEN];
        #pragma unroll
        for (int i = 0; i < U; i++) {
            state = tanh_fast(uv[i] + fmaf(state, g, be));
            __nv_bfloat16 hi = __float2bfloat16(state);
            size_t off = (size_t)(s0 + i) * (2 * HIDDEN);
            sp[off]          = hi;
            sp[off + HIDDEN] = __float2bfloat16(state - __bfloat162float(hi));
        }
    }
}

// ---------------------------------------------------------------------------
// Launch
// ---------------------------------------------------------------------------
extern "C" void kernel_launch(void* const* d_in, const int* in_sizes, int n_in,
                              void* d_out, int out_size)
{
    const float* x     = (const float*)d_in[0];  // [B,S,D]
    const float* W_in  = (const float*)d_in[1];  // [H,D]
    const float* b_in  = (const float*)d_in[2];  // [H]
    const float* W_out = (const float*)d_in[3];  // [D,H]
    const float* b_out = (const float*)d_in[4];  // [D]
    const float* gamma = (const float*)d_in[5];  // [H]
    const float* beta  = (const float*)d_in[6];  // [H]
    float* y = (float*)d_out;                    // [B,S,D]

    __nv_bfloat16 *Ae1, *Be1, *As2, *Be2;
    float* u;
    cudaGetSymbolAddress((void**)&Ae1, g_Ae1);
    cudaGetSymbolAddress((void**)&Be1, g_Be1);
    cudaGetSymbolAddress((void**)&u,   g_u);
    cudaGetSymbolAddress((void**)&As2, g_As2);
    cudaGetSymbolAddress((void**)&Be2, g_Be2);

    const int smem_bytes = 3 * STAGE_BYTES + 1024;   // 99328
    cudaFuncSetAttribute(gemm_mma, cudaFuncAttributeMaxDynamicSharedMemorySize, smem_bytes);

    // Split conversions
    split_kernel<<<2048, 256>>>(x,     Ae1, 11, (size_t)MROWS  * DIMD   / 4);
    split_kernel<<<1024, 256>>>(W_in,  Be1, 11, (size_t)HIDDEN * DIMD   / 4);
    split_kernel<<<1024, 256>>>(W_out, Be2, 12, (size_t)DIMD   * HIDDEN / 4);

    // GEMM1: u = x @ W_in^T + b_in    (M=8192, N=4096, K=2048 -> KT=96)
    {
        dim3 grid(HIDDEN / 128, MROWS / 128);
        gemm_mma<<<grid, 256, smem_bytes>>>(Ae1, Be1, b_in, u, HIDDEN, DIMD, 3 * (DIMD / 64));
    }

    // Recurrence + split of states (256 blocks x 64 threads)
    recurrence_split<<<(BATCH * HIDDEN) / 64, 64>>>(u, gamma, beta, As2);

    // GEMM2: y = states @ W_out^T + b_out  (M=8192, N=2048, K=4096 -> KT=192)
    {
        dim3 grid(DIMD / 128, MROWS / 128);
        gemm_mma<<<grid, 256, smem_bytes>>>(As2, Be2, b_out, y, DIMD, HIDDEN, 3 * (HIDDEN / 64));
    }
}